// round 1
// baseline (speedup 1.0000x reference)
#include <cuda_runtime.h>
#include <cstdint>

// ---------------------------------------------------------------------------
// Problem constants (fixed by reference: B=1024, D=16384, K=8, NEG_RATIO=6,
// SAMPLE_SEED=42)
// ---------------------------------------------------------------------------
#define BB      1024
#define DD      16384
#define NTOT    (BB * DD)          // 16,777,216
#define HH      (NTOT / 2)         // 8,388,608 (legacy split-counter half)
#define NNEG    48                 // 6 * K
#define CAP     512                // boundary-bucket candidate capacity
#define LOBKT   224                // conditional histogram low bucket
#define T1      256
#define T2      256
#define NB1     (NTOT / (T1 * 8))  // 8192 kernel-1 blocks

// JAX default since 0.4.30: jax_threefry_partitionable=True.
// If bench rel_err comes back ~5e-3, flip this to 0 (legacy split-counter).
#define PARTITIONABLE 1

// ---------------------------------------------------------------------------
// Scratch (static __device__ arrays — no runtime allocation)
// ---------------------------------------------------------------------------
__device__ unsigned short g_keys[NTOT];   // 32 MB: top 16 bits of noise word (0 if positive/masked)
__device__ float g_part1[NB1];            // kernel-1 partial sums (positive-term loss)
__device__ float g_part2[BB];             // kernel-2 per-row sums (negative-term loss)

// ---------------------------------------------------------------------------
// threefry2x32, key = (0, 42)  — exact JAX schedule
// ---------------------------------------------------------------------------
__device__ __forceinline__ void tf2x32(unsigned c0, unsigned c1,
                                       unsigned &o0, unsigned &o1) {
    const unsigned ks0 = 0u;
    const unsigned ks1 = 42u;
    const unsigned ks2 = 0u ^ 42u ^ 0x1BD11BDAu;
    unsigned x0 = c0 + ks0;
    unsigned x1 = c1 + ks1;
#define TFR(R) { x0 += x1; x1 = __funnelshift_l(x1, x1, (R)); x1 ^= x0; }
    TFR(13) TFR(15) TFR(26) TFR(6)
    x0 += ks1; x1 += ks2 + 1u;
    TFR(17) TFR(29) TFR(16) TFR(24)
    x0 += ks2; x1 += ks0 + 2u;
    TFR(13) TFR(15) TFR(26) TFR(6)
    x0 += ks0; x1 += ks1 + 3u;
    TFR(17) TFR(29) TFR(16) TFR(24)
    x0 += ks1; x1 += ks2 + 4u;
    TFR(13) TFR(15) TFR(26) TFR(6)
    x0 += ks2; x1 += ks0 + 5u;
#undef TFR
    o0 = x0; o1 = x1;
}

// Random 32-bit word for flat element index f (row-major over [B, D]).
__device__ __forceinline__ unsigned noise_bits(unsigned f) {
#if PARTITIONABLE
    // partitionable path: per-element 64-bit counter (hi=0, lo=f), out = o0 ^ o1
    unsigned o0, o1;
    tf2x32(0u, f, o0, o1);
    return o0 ^ o1;
#else
    // legacy path: counts split in halves; element f<H -> o0 of (f, f+H),
    // f>=H -> o1 of (f-H, f)
    unsigned o0, o1;
    if (f < (unsigned)HH) { tf2x32(f, f + (unsigned)HH, o0, o1); return o0; }
    else                  { tf2x32(f - (unsigned)HH, f, o0, o1); return o1; }
#endif
}

// softplus matching jax.nn.softplus (logaddexp(x, 0)) in fp32
__device__ __forceinline__ float softplus_f(float x) {
    return fmaxf(x, 0.f) + log1pf(__expf(-fabsf(x)));
}

// ---------------------------------------------------------------------------
// Kernel 1: generate noise keys (16-bit truncation), mask positives,
//           accumulate positive-term loss.
// ---------------------------------------------------------------------------
__global__ void __launch_bounds__(T1)
k1_gen(const float* __restrict__ pred, const float* __restrict__ target) {
    __shared__ float warpbuf[T1 / 32];
    const unsigned base = (blockIdx.x * (unsigned)T1 + threadIdx.x) * 8u;

    float t[8];
    *reinterpret_cast<float4*>(&t[0]) = *reinterpret_cast<const float4*>(target + base);
    *reinterpret_cast<float4*>(&t[4]) = *reinterpret_cast<const float4*>(target + base + 4);

    unsigned short kk[8];
    float pos = 0.f;
#pragma unroll
    for (int q = 0; q < 8; q++) {
        unsigned f = base + (unsigned)q;
        unsigned bits = noise_bits(f);
        if (t[q] > 0.f) {
            kk[q] = 0;                          // masked: noise := -1, never sampled
            pos += softplus_f(-pred[f]);        // BCE positive term: softplus(-x)
        } else {
            kk[q] = (unsigned short)(bits >> 16);
        }
    }

    uint4 v;
    v.x = (unsigned)kk[0] | ((unsigned)kk[1] << 16);
    v.y = (unsigned)kk[2] | ((unsigned)kk[3] << 16);
    v.z = (unsigned)kk[4] | ((unsigned)kk[5] << 16);
    v.w = (unsigned)kk[6] | ((unsigned)kk[7] << 16);
    *reinterpret_cast<uint4*>(g_keys + base) = v;

    // deterministic block reduction of the positive-term partial
    for (int off = 16; off; off >>= 1) pos += __shfl_down_sync(0xFFFFFFFFu, pos, off);
    if ((threadIdx.x & 31) == 0) warpbuf[threadIdx.x >> 5] = pos;
    __syncthreads();
    if (threadIdx.x == 0) {
        float s = 0.f;
        for (int w = 0; w < T1 / 32; w++) s += warpbuf[w];
        g_part1[blockIdx.x] = s;
    }
}

// ---------------------------------------------------------------------------
// Kernel 2: per-row exact top-48 selection (radix on top-8 bits, exact
//           boundary-bucket ranking with JAX top_k lower-index tie-break),
//           accumulate negative-term loss.
// ---------------------------------------------------------------------------
__global__ void __launch_bounds__(T2)
k2_select(const float* __restrict__ pred) {
    __shared__ unsigned short skey[DD];          // 32 KB
    __shared__ int hist[256];
    __shared__ unsigned long long ckey[CAP];
    __shared__ float warpbuf[T2 / 32];
    __shared__ int s_bsel, s_r, s_flag, s_ccount;

    const int row = blockIdx.x;
    const int tid = threadIdx.x;
    const unsigned rowbase = (unsigned)row * DD;
    const unsigned short* gk = g_keys + rowbase;
    const float* prow = pred + rowbase;

    // Load row keys to smem (128-bit loads: 8 keys each)
    for (int i = tid; i < DD / 8; i += T2)
        reinterpret_cast<uint4*>(skey)[i] = reinterpret_cast<const uint4*>(gk)[i];
    for (int i = tid; i < 256; i += T2) hist[i] = 0;
    if (tid == 0) { s_flag = 0; s_ccount = 0; }
    __syncthreads();

    // Conditional histogram of top-8 bits (only the high region matters;
    // P(cutoff below bucket 224) is ~0 for 16336 uniform samples, top-48)
    for (int j = tid; j < DD; j += T2) {
        int b = skey[j] >> 8;
        if (b >= LOBKT) atomicAdd(&hist[b], 1);
    }
    __syncthreads();
    if (tid == 0) {
        int acc = 0, bsel = -1, r = 0;
        for (int b = 255; b >= LOBKT; b--) {
            int c = hist[b];
            if (acc + c >= NNEG) { bsel = b; r = NNEG - acc; break; }
            acc += c;
        }
        if (bsel < 0) s_flag = 1;
        else { s_bsel = bsel; s_r = r; }
    }
    __syncthreads();
    if (s_flag) {  // astronomically rare exact fallback: full-range recount
        for (int i = tid; i < 256; i += T2) hist[i] = 0;
        __syncthreads();
        for (int j = tid; j < DD; j += T2) atomicAdd(&hist[skey[j] >> 8], 1);
        __syncthreads();
        if (tid == 0) {
            int acc = 0;
            for (int b = 255; b >= 0; b--) {
                int c = hist[b];
                if (acc + c >= NNEG) { s_bsel = b; s_r = NNEG - acc; break; }
                acc += c;
            }
        }
        __syncthreads();
    }
    const int bsel = s_bsel;
    const int r = s_r;

    // Pass B: buckets > bsel are certainly selected; bucket == bsel -> candidates
    float acc = 0.f;
    for (int j = tid; j < DD; j += T2) {
        int b = skey[j] >> 8;
        if (b > bsel) {
            acc += softplus_f(prow[j]);
        } else if (b == bsel) {
            int p = atomicAdd(&s_ccount, 1);
            if (p < CAP) ckey[p] = (unsigned long long)(unsigned)j;  // temp: store j
        }
    }
    __syncthreads();

    // Recompute full noise word for candidates, build composite sort key:
    // (v = bits>>9) major, (D-1-j) minor  => ties prefer LOWER index (JAX top_k)
    const int C = min(s_ccount, CAP);
    for (int i = tid; i < C; i += T2) {
        unsigned j = (unsigned)ckey[i];
        unsigned bits = noise_bits(rowbase + j);
        unsigned v = bits >> 9;
        ckey[i] = (((unsigned long long)v) << 14) |
                  (unsigned long long)((unsigned)DD - 1u - j);
    }
    __syncthreads();

    // Exact rank selection of the top-r candidates (C ~ 64, O(C^2) trivial)
    for (int i = tid; i < C; i += T2) {
        unsigned long long kme = ckey[i];
        int rank = 0;
        for (int t = 0; t < C; t++) rank += (ckey[t] > kme) ? 1 : 0;
        if (rank < r) {
            unsigned j = (unsigned)DD - 1u - (unsigned)(kme & 0x3FFFULL);
            acc += softplus_f(prow[j]);
        }
    }

    // block reduce -> per-row partial
    for (int off = 16; off; off >>= 1) acc += __shfl_down_sync(0xFFFFFFFFu, acc, off);
    if ((tid & 31) == 0) warpbuf[tid >> 5] = acc;
    __syncthreads();
    if (tid == 0) {
        float s = 0.f;
        for (int w = 0; w < T2 / 32; w++) s += warpbuf[w];
        g_part2[row] = s;
    }
}

// ---------------------------------------------------------------------------
// Kernel 3: deterministic final reduction of all partials -> out[0]
// ---------------------------------------------------------------------------
__global__ void __launch_bounds__(256)
k3_reduce(float* __restrict__ out) {
    __shared__ float warpbuf[8];
    float v = 0.f;
    for (int i = threadIdx.x; i < NB1; i += 256) v += g_part1[i];
    for (int i = threadIdx.x; i < BB;  i += 256) v += g_part2[i];
    for (int off = 16; off; off >>= 1) v += __shfl_down_sync(0xFFFFFFFFu, v, off);
    if ((threadIdx.x & 31) == 0) warpbuf[threadIdx.x >> 5] = v;
    __syncthreads();
    if (threadIdx.x == 0) {
        float s = 0.f;
        for (int w = 0; w < 8; w++) s += warpbuf[w];
        out[0] = s;
    }
}

// ---------------------------------------------------------------------------
// Launch: inputs per metadata order: pred [B*D] f32, target [B*D] f32, k (unused,
// compile-time constant 8). Output: 1 float.
// ---------------------------------------------------------------------------
extern "C" void kernel_launch(void* const* d_in, const int* in_sizes, int n_in,
                              void* d_out, int out_size) {
    const float* pred   = (const float*)d_in[0];
    const float* target = (const float*)d_in[1];
    (void)in_sizes; (void)n_in; (void)out_size;

    k1_gen<<<NB1, T1>>>(pred, target);
    k2_select<<<BB, T2>>>(pred);
    k3_reduce<<<1, 256>>>((float*)d_out);
}